// round 1
// baseline (speedup 1.0000x reference)
#include <cuda_runtime.h>
#include <math.h>

#define S 4096
#define D 2048
#define FF 8192
#define DH (D/2)
#define EPSF 1.1920929e-07f

// ---------------- scratch (device globals; allocation-free) ----------------
__device__ float g_h[S * D];      // rmsnorm output (reused for both norms)
__device__ float g_q[S * D];
__device__ float g_k[S * D];
__device__ float g_v[S * D];
__device__ float g_attn[(size_t)S * S];
__device__ float g_av[S * D];
__device__ float g_res1[S * D];
__device__ float g_g[S * FF];     // gate (later silu(g)*u in place)
__device__ float g_u[S * FF];

// ---------------- RMSNorm: one block per row ----------------
__global__ void rmsnorm_kernel(const float* __restrict__ x,
                               const float* __restrict__ w,
                               float* __restrict__ out) {
    const int row = blockIdx.x;
    const float* xr = x + (size_t)row * D;
    float ss = 0.f;
    for (int i = threadIdx.x; i < D; i += blockDim.x) {
        float v = xr[i];
        ss += v * v;
    }
    __shared__ float red[32];
    int lane = threadIdx.x & 31, wid = threadIdx.x >> 5;
    #pragma unroll
    for (int o = 16; o > 0; o >>= 1) ss += __shfl_xor_sync(0xFFFFFFFFu, ss, o);
    if (lane == 0) red[wid] = ss;
    __syncthreads();
    if (wid == 0) {
        float v = (lane < (blockDim.x >> 5)) ? red[lane] : 0.f;
        #pragma unroll
        for (int o = 16; o > 0; o >>= 1) v += __shfl_xor_sync(0xFFFFFFFFu, v, o);
        if (lane == 0) red[0] = v;
    }
    __syncthreads();
    const float inv = rsqrtf(red[0] / (float)D + EPSF);
    for (int i = threadIdx.x; i < D; i += blockDim.x)
        out[(size_t)row * D + i] = xr[i] * inv * w[i];
}

// ---------------- RoPE on q and k (in place) ----------------
__global__ void rope_kernel(float* __restrict__ q, float* __restrict__ k,
                            const float* __restrict__ cosb,
                            const float* __restrict__ sinb) {
    int idx = blockIdx.x * blockDim.x + threadIdx.x;  // over S*DH
    if (idx >= S * DH) return;
    int s = idx / DH, i = idx % DH;
    float c = cosb[(size_t)s * DH + i];
    float sn = sinb[(size_t)s * DH + i];
    size_t b = (size_t)s * D + i;
    float q1 = q[b], q2 = q[b + DH];
    q[b]      = q1 * c - q2 * sn;
    q[b + DH] = q1 * sn + q2 * c;
    float k1 = k[b], k2 = k[b + DH];
    k[b]      = k1 * c - k2 * sn;
    k[b + DH] = k1 * sn + k2 * c;
}

// ---------------- row softmax over S=4096, one block per row ----------------
__global__ void softmax_kernel(float* __restrict__ attn) {
    const int row = blockIdx.x;
    float* a = attn + (size_t)row * S;
    __shared__ float sbuf[S];
    __shared__ float red[32];
    int lane = threadIdx.x & 31, wid = threadIdx.x >> 5;

    float lmax = -3.402823e38f;
    for (int i = threadIdx.x; i < S; i += blockDim.x) {
        float v = a[i];
        sbuf[i] = v;
        lmax = fmaxf(lmax, v);
    }
    #pragma unroll
    for (int o = 16; o > 0; o >>= 1) lmax = fmaxf(lmax, __shfl_xor_sync(0xFFFFFFFFu, lmax, o));
    if (lane == 0) red[wid] = lmax;
    __syncthreads();
    if (wid == 0) {
        float v = (lane < (blockDim.x >> 5)) ? red[lane] : -3.402823e38f;
        #pragma unroll
        for (int o = 16; o > 0; o >>= 1) v = fmaxf(v, __shfl_xor_sync(0xFFFFFFFFu, v, o));
        if (lane == 0) red[0] = v;
    }
    __syncthreads();
    const float m = red[0];
    __syncthreads();

    float lsum = 0.f;
    for (int i = threadIdx.x; i < S; i += blockDim.x) {
        float e = __expf(sbuf[i] - m);
        sbuf[i] = e;
        lsum += e;
    }
    #pragma unroll
    for (int o = 16; o > 0; o >>= 1) lsum += __shfl_xor_sync(0xFFFFFFFFu, lsum, o);
    if (lane == 0) red[wid] = lsum;
    __syncthreads();
    if (wid == 0) {
        float v = (lane < (blockDim.x >> 5)) ? red[lane] : 0.f;
        #pragma unroll
        for (int o = 16; o > 0; o >>= 1) v += __shfl_xor_sync(0xFFFFFFFFu, v, o);
        if (lane == 0) red[0] = v;
    }
    __syncthreads();
    const float inv = 1.0f / red[0];
    for (int i = threadIdx.x; i < S; i += blockDim.x)
        a[i] = sbuf[i] * inv;
}

// ---------------- SwiGLU: g = silu(g) * u ----------------
__global__ void swiglu_kernel(float* __restrict__ g, const float* __restrict__ u) {
    size_t idx = (size_t)blockIdx.x * blockDim.x + threadIdx.x;
    if (idx >= (size_t)S * FF) return;
    float gv = g[idx];
    float sv = gv / (1.0f + __expf(-gv));
    g[idx] = sv * u[idx];
}

// ---------------- GEMM TN: C[M,N] = alpha * A[M,K] @ B[N,K]^T (+ Cadd) ------
// Both A and B are K-major. Tiles 128x128x16, 256 threads, 8x8 per thread
// with the 64-offset quadrant layout.
#define BM 128
#define BN 128
#define BK 16

__global__ __launch_bounds__(256, 2)
void gemm_tn_kernel(const float* __restrict__ A, const float* __restrict__ B,
                    const float* __restrict__ Cadd, float* __restrict__ Cout,
                    int M, int N, int K, float alpha) {
    __shared__ float As[BK][BM + 4];
    __shared__ float Bs[BK][BN + 4];
    const int tid = threadIdx.x;
    const int m0 = blockIdx.y * BM, n0 = blockIdx.x * BN;
    const int tm = tid >> 4, tn = tid & 15;

    float acc[8][8];
    #pragma unroll
    for (int i = 0; i < 8; i++)
        #pragma unroll
        for (int j = 0; j < 8; j++) acc[i][j] = 0.f;

    for (int k0 = 0; k0 < K; k0 += BK) {
        #pragma unroll
        for (int it = 0; it < 2; it++) {
            int lin = tid + it * 256;
            int row = lin >> 2;
            int c4  = (lin & 3) << 2;
            float4 va = *reinterpret_cast<const float4*>(&A[(size_t)(m0 + row) * K + k0 + c4]);
            As[c4 + 0][row] = va.x; As[c4 + 1][row] = va.y;
            As[c4 + 2][row] = va.z; As[c4 + 3][row] = va.w;
            float4 vb = *reinterpret_cast<const float4*>(&B[(size_t)(n0 + row) * K + k0 + c4]);
            Bs[c4 + 0][row] = vb.x; Bs[c4 + 1][row] = vb.y;
            Bs[c4 + 2][row] = vb.z; Bs[c4 + 3][row] = vb.w;
        }
        __syncthreads();
        #pragma unroll
        for (int kk = 0; kk < BK; kk++) {
            float4 a0 = *reinterpret_cast<const float4*>(&As[kk][tm * 4]);
            float4 a1 = *reinterpret_cast<const float4*>(&As[kk][64 + tm * 4]);
            float4 b0 = *reinterpret_cast<const float4*>(&Bs[kk][tn * 4]);
            float4 b1 = *reinterpret_cast<const float4*>(&Bs[kk][64 + tn * 4]);
            float a[8] = {a0.x, a0.y, a0.z, a0.w, a1.x, a1.y, a1.z, a1.w};
            float b[8] = {b0.x, b0.y, b0.z, b0.w, b1.x, b1.y, b1.z, b1.w};
            #pragma unroll
            for (int i = 0; i < 8; i++)
                #pragma unroll
                for (int j = 0; j < 8; j++) acc[i][j] = fmaf(a[i], b[j], acc[i][j]);
        }
        __syncthreads();
    }

    #pragma unroll
    for (int i = 0; i < 8; i++) {
        int m = m0 + ((i < 4) ? (tm * 4 + i) : (64 + tm * 4 + (i - 4)));
        #pragma unroll
        for (int jq = 0; jq < 2; jq++) {
            int n = n0 + jq * 64 + tn * 4;
            float4 r;
            r.x = acc[i][jq * 4 + 0] * alpha;
            r.y = acc[i][jq * 4 + 1] * alpha;
            r.z = acc[i][jq * 4 + 2] * alpha;
            r.w = acc[i][jq * 4 + 3] * alpha;
            if (Cadd) {
                float4 c = *reinterpret_cast<const float4*>(&Cadd[(size_t)m * N + n]);
                r.x += c.x; r.y += c.y; r.z += c.z; r.w += c.w;
            }
            *reinterpret_cast<float4*>(&Cout[(size_t)m * N + n]) = r;
        }
    }
}

// ---------------- GEMM NN: C[M,N] = A[M,K] @ B[K,N] (+ Cadd) ----------------
__global__ __launch_bounds__(256, 2)
void gemm_nn_kernel(const float* __restrict__ A, const float* __restrict__ B,
                    const float* __restrict__ Cadd, float* __restrict__ Cout,
                    int M, int N, int K, float alpha) {
    __shared__ float As[BK][BM + 4];
    __shared__ float Bs[BK][BN + 4];
    const int tid = threadIdx.x;
    const int m0 = blockIdx.y * BM, n0 = blockIdx.x * BN;
    const int tm = tid >> 4, tn = tid & 15;

    float acc[8][8];
    #pragma unroll
    for (int i = 0; i < 8; i++)
        #pragma unroll
        for (int j = 0; j < 8; j++) acc[i][j] = 0.f;

    for (int k0 = 0; k0 < K; k0 += BK) {
        #pragma unroll
        for (int it = 0; it < 2; it++) {
            int lin = tid + it * 256;
            int row = lin >> 2;
            int c4  = (lin & 3) << 2;
            float4 va = *reinterpret_cast<const float4*>(&A[(size_t)(m0 + row) * K + k0 + c4]);
            As[c4 + 0][row] = va.x; As[c4 + 1][row] = va.y;
            As[c4 + 2][row] = va.z; As[c4 + 3][row] = va.w;
            int kr = lin >> 5;
            int nc = (lin & 31) << 2;
            float4 vb = *reinterpret_cast<const float4*>(&B[(size_t)(k0 + kr) * N + n0 + nc]);
            *reinterpret_cast<float4*>(&Bs[kr][nc]) = vb;
        }
        __syncthreads();
        #pragma unroll
        for (int kk = 0; kk < BK; kk++) {
            float4 a0 = *reinterpret_cast<const float4*>(&As[kk][tm * 4]);
            float4 a1 = *reinterpret_cast<const float4*>(&As[kk][64 + tm * 4]);
            float4 b0 = *reinterpret_cast<const float4*>(&Bs[kk][tn * 4]);
            float4 b1 = *reinterpret_cast<const float4*>(&Bs[kk][64 + tn * 4]);
            float a[8] = {a0.x, a0.y, a0.z, a0.w, a1.x, a1.y, a1.z, a1.w};
            float b[8] = {b0.x, b0.y, b0.z, b0.w, b1.x, b1.y, b1.z, b1.w};
            #pragma unroll
            for (int i = 0; i < 8; i++)
                #pragma unroll
                for (int j = 0; j < 8; j++) acc[i][j] = fmaf(a[i], b[j], acc[i][j]);
        }
        __syncthreads();
    }

    #pragma unroll
    for (int i = 0; i < 8; i++) {
        int m = m0 + ((i < 4) ? (tm * 4 + i) : (64 + tm * 4 + (i - 4)));
        #pragma unroll
        for (int jq = 0; jq < 2; jq++) {
            int n = n0 + jq * 64 + tn * 4;
            float4 r;
            r.x = acc[i][jq * 4 + 0] * alpha;
            r.y = acc[i][jq * 4 + 1] * alpha;
            r.z = acc[i][jq * 4 + 2] * alpha;
            r.w = acc[i][jq * 4 + 3] * alpha;
            if (Cadd) {
                float4 c = *reinterpret_cast<const float4*>(&Cadd[(size_t)m * N + n]);
                r.x += c.x; r.y += c.y; r.z += c.z; r.w += c.w;
            }
            *reinterpret_cast<float4*>(&Cout[(size_t)m * N + n]) = r;
        }
    }
}

// ---------------- host launcher ----------------
extern "C" void kernel_launch(void* const* d_in, const int* in_sizes, int n_in,
                              void* d_out, int out_size) {
    const float* x      = (const float*)d_in[0];
    const float* w_rn1  = (const float*)d_in[1];
    const float* wq     = (const float*)d_in[2];
    const float* wk     = (const float*)d_in[3];
    const float* wv     = (const float*)d_in[4];
    const float* wo     = (const float*)d_in[5];
    const float* w_rn2  = (const float*)d_in[6];
    const float* w_gate = (const float*)d_in[7];
    const float* w_up   = (const float*)d_in[8];
    const float* w_down = (const float*)d_in[9];
    const float* cosb   = (const float*)d_in[10];
    const float* sinb   = (const float*)d_in[11];
    float* out = (float*)d_out;

    float *h, *q, *k, *v, *attn, *av, *res1, *g, *u;
    cudaGetSymbolAddress((void**)&h,    g_h);
    cudaGetSymbolAddress((void**)&q,    g_q);
    cudaGetSymbolAddress((void**)&k,    g_k);
    cudaGetSymbolAddress((void**)&v,    g_v);
    cudaGetSymbolAddress((void**)&attn, g_attn);
    cudaGetSymbolAddress((void**)&av,   g_av);
    cudaGetSymbolAddress((void**)&res1, g_res1);
    cudaGetSymbolAddress((void**)&g,    g_g);
    cudaGetSymbolAddress((void**)&u,    g_u);

    const float inv_scale = 1.0f / sqrtf((float)D);

    // 1. h = rmsnorm(x, w_rn1)
    rmsnorm_kernel<<<S, 256>>>(x, w_rn1, h);

    // 2. q/k/v projections (TN: W is [out,in])
    {
        dim3 grid(D / BN, S / BM);
        gemm_tn_kernel<<<grid, 256>>>(h, wq, nullptr, q, S, D, D, 1.0f);
        gemm_tn_kernel<<<grid, 256>>>(h, wk, nullptr, k, S, D, D, 1.0f);
        gemm_tn_kernel<<<grid, 256>>>(h, wv, nullptr, v, S, D, D, 1.0f);
    }

    // 3. RoPE on q, k
    rope_kernel<<<(S * DH + 255) / 256, 256>>>(q, k, cosb, sinb);

    // 4. attn = q @ k^T / sqrt(D)   (TN since both are K(=D)-major)
    {
        dim3 grid(S / BN, S / BM);
        gemm_tn_kernel<<<grid, 256>>>(q, k, nullptr, attn, S, S, D, inv_scale);
    }

    // 5. softmax rows
    softmax_kernel<<<S, 256>>>(attn);

    // 6. av = attn @ v  (NN)
    {
        dim3 grid(D / BN, S / BM);
        gemm_nn_kernel<<<grid, 256>>>(attn, v, nullptr, av, S, D, S, 1.0f);
    }

    // 7. res1 = x + av @ wo^T
    {
        dim3 grid(D / BN, S / BM);
        gemm_tn_kernel<<<grid, 256>>>(av, wo, x, res1, S, D, D, 1.0f);
    }

    // 8. h = rmsnorm(res1, w_rn2)
    rmsnorm_kernel<<<S, 256>>>(res1, w_rn2, h);

    // 9. gate / up projections
    {
        dim3 grid(FF / BN, S / BM);
        gemm_tn_kernel<<<grid, 256>>>(h, w_gate, nullptr, g, S, FF, D, 1.0f);
        gemm_tn_kernel<<<grid, 256>>>(h, w_up,   nullptr, u, S, FF, D, 1.0f);
    }

    // 10. g = silu(g) * u
    {
        size_t tot = (size_t)S * FF;
        swiglu_kernel<<<(unsigned)((tot + 255) / 256), 256>>>(g, u);
    }

    // 11. out = res1 + g @ w_down^T
    {
        dim3 grid(D / BN, S / BM);
        gemm_tn_kernel<<<grid, 256>>>(g, w_down, res1, out, S, D, FF, 1.0f);
    }
}

// round 4
// speedup vs baseline: 2.2046x; 2.2046x over previous
#include <cuda_runtime.h>
#include <cuda_bf16.h>
#include <math.h>

#define S 4096
#define D 2048
#define FF 8192
#define DH (D/2)
#define EPSF 1.1920929e-07f

typedef __nv_bfloat16 bf16;

// ---------------- scratch (device globals) ----------------
__device__ float g_res1[S * D];
__device__ bf16 g_hb_h[S * D],  g_hb_l[S * D];
__device__ bf16 g_qb_h[S * D],  g_qb_l[S * D];
__device__ bf16 g_kb_h[S * D],  g_kb_l[S * D];
__device__ bf16 g_vb_h[S * D],  g_vb_l[S * D];
__device__ bf16 g_avb_h[S * D], g_avb_l[S * D];
__device__ bf16 g_gateb_h[S * FF], g_gateb_l[S * FF];
// attn bf16 pair (S*S) aliases the front of the up buffers (disjoint lifetimes:
// attn consumed at step 8; up written at step 12).
__device__ bf16 g_upb_h[S * FF], g_upb_l[S * FF];
__device__ bf16 g_wq_h[D * D],  g_wq_l[D * D];
__device__ bf16 g_wk_h[D * D],  g_wk_l[D * D];
__device__ bf16 g_wv_h[D * D],  g_wv_l[D * D];
__device__ bf16 g_wo_h[D * D],  g_wo_l[D * D];
__device__ bf16 g_wg_h[FF * D], g_wg_l[FF * D];
__device__ bf16 g_wu_h[FF * D], g_wu_l[FF * D];
__device__ bf16 g_wd_h[D * FF], g_wd_l[D * FF];

// ---------------- helpers ----------------
__device__ __forceinline__ void split2(float x, bf16& hi, bf16& lo) {
    hi = __float2bfloat16(x);
    lo = __float2bfloat16(x - __bfloat162float(hi));
}
__device__ __forceinline__ float join2(bf16 hi, bf16 lo) {
    return __bfloat162float(hi) + __bfloat162float(lo);
}
__device__ __forceinline__ unsigned saddr(const void* p) {
    return (unsigned)__cvta_generic_to_shared(p);
}
__device__ __forceinline__ void ldmx4(unsigned* r, unsigned a) {
    asm volatile("ldmatrix.sync.aligned.m8n8.x4.shared.b16 {%0,%1,%2,%3}, [%4];\n"
                 : "=r"(r[0]), "=r"(r[1]), "=r"(r[2]), "=r"(r[3]) : "r"(a));
}
__device__ __forceinline__ void ldmx4t(unsigned* r, unsigned a) {
    asm volatile("ldmatrix.sync.aligned.m8n8.x4.trans.shared.b16 {%0,%1,%2,%3}, [%4];\n"
                 : "=r"(r[0]), "=r"(r[1]), "=r"(r[2]), "=r"(r[3]) : "r"(a));
}
__device__ __forceinline__ void mma16816(float* c, const unsigned* a, const unsigned* b) {
    asm volatile("mma.sync.aligned.m16n8k16.row.col.f32.bf16.bf16.f32 "
                 "{%0,%1,%2,%3}, {%4,%5,%6,%7}, {%8,%9}, {%0,%1,%2,%3};\n"
                 : "+f"(c[0]), "+f"(c[1]), "+f"(c[2]), "+f"(c[3])
                 : "r"(a[0]), "r"(a[1]), "r"(a[2]), "r"(a[3]), "r"(b[0]), "r"(b[1]));
}

// ---------------- weight split ----------------
__global__ void convert_split4(const float4* __restrict__ x,
                               __nv_bfloat162* __restrict__ hi,
                               __nv_bfloat162* __restrict__ lo, int n4) {
    int i = blockIdx.x * blockDim.x + threadIdx.x;
    if (i >= n4) return;
    float4 v = x[i];
    __nv_bfloat162 h0, h1, l0, l1;
    split2(v.x, h0.x, l0.x); split2(v.y, h0.y, l0.y);
    split2(v.z, h1.x, l1.x); split2(v.w, h1.y, l1.y);
    hi[2 * i] = h0; hi[2 * i + 1] = h1;
    lo[2 * i] = l0; lo[2 * i + 1] = l1;
}

// ---------------- RMSNorm (fp32 in) -> bf16 pair ----------------
__global__ void rmsnorm_split(const float* __restrict__ x, const float* __restrict__ w,
                              bf16* __restrict__ oh, bf16* __restrict__ ol) {
    const int row = blockIdx.x;
    const float* xr = x + (size_t)row * D;
    float ss = 0.f;
    for (int i = threadIdx.x; i < D; i += blockDim.x) { float v = xr[i]; ss += v * v; }
    __shared__ float red[32];
    int lane = threadIdx.x & 31, wid = threadIdx.x >> 5;
    #pragma unroll
    for (int o = 16; o > 0; o >>= 1) ss += __shfl_xor_sync(0xFFFFFFFFu, ss, o);
    if (lane == 0) red[wid] = ss;
    __syncthreads();
    if (wid == 0) {
        float v = (lane < (blockDim.x >> 5)) ? red[lane] : 0.f;
        #pragma unroll
        for (int o = 16; o > 0; o >>= 1) v += __shfl_xor_sync(0xFFFFFFFFu, v, o);
        if (lane == 0) red[0] = v;
    }
    __syncthreads();
    const float inv = rsqrtf(red[0] / (float)D + EPSF);
    for (int i = threadIdx.x; i < D; i += blockDim.x) {
        float v = xr[i] * inv * w[i];
        bf16 h, l; split2(v, h, l);
        oh[(size_t)row * D + i] = h; ol[(size_t)row * D + i] = l;
    }
}

// ---------------- RoPE on bf16 pairs, in place ----------------
__global__ void rope_pair(bf16* __restrict__ qh, bf16* __restrict__ ql,
                          bf16* __restrict__ kh, bf16* __restrict__ kl,
                          const float* __restrict__ cosb, const float* __restrict__ sinb) {
    int idx = blockIdx.x * blockDim.x + threadIdx.x;
    if (idx >= S * DH) return;
    int s = idx / DH, i = idx % DH;
    float c = cosb[(size_t)s * DH + i];
    float sn = sinb[(size_t)s * DH + i];
    size_t b = (size_t)s * D + i;
    float q1 = join2(qh[b], ql[b]);
    float q2 = join2(qh[b + DH], ql[b + DH]);
    float k1 = join2(kh[b], kl[b]);
    float k2 = join2(kh[b + DH], kl[b + DH]);
    bf16 h, l;
    split2(q1 * c - q2 * sn, h, l);  qh[b] = h;      ql[b] = l;
    split2(q1 * sn + q2 * c, h, l);  qh[b + DH] = h; ql[b + DH] = l;
    split2(k1 * c - k2 * sn, h, l);  kh[b] = h;      kl[b] = l;
    split2(k1 * sn + k2 * c, h, l);  kh[b + DH] = h; kl[b + DH] = l;
}

// ---------------- softmax on bf16 pair rows (in place) ----------------
__global__ void softmax_pair(bf16* __restrict__ ah, bf16* __restrict__ al) {
    const int row = blockIdx.x;
    bf16* ph = ah + (size_t)row * S;
    bf16* pl = al + (size_t)row * S;
    __shared__ float sbuf[S];
    __shared__ float red[32];
    int lane = threadIdx.x & 31, wid = threadIdx.x >> 5;

    float lmax = -3.402823e38f;
    for (int i = threadIdx.x; i < S; i += blockDim.x) {
        float v = join2(ph[i], pl[i]);
        sbuf[i] = v; lmax = fmaxf(lmax, v);
    }
    #pragma unroll
    for (int o = 16; o > 0; o >>= 1) lmax = fmaxf(lmax, __shfl_xor_sync(0xFFFFFFFFu, lmax, o));
    if (lane == 0) red[wid] = lmax;
    __syncthreads();
    if (wid == 0) {
        float v = (lane < (blockDim.x >> 5)) ? red[lane] : -3.402823e38f;
        #pragma unroll
        for (int o = 16; o > 0; o >>= 1) v = fmaxf(v, __shfl_xor_sync(0xFFFFFFFFu, v, o));
        if (lane == 0) red[0] = v;
    }
    __syncthreads();
    const float m = red[0];
    __syncthreads();

    float lsum = 0.f;
    for (int i = threadIdx.x; i < S; i += blockDim.x) {
        float e = __expf(sbuf[i] - m); sbuf[i] = e; lsum += e;
    }
    #pragma unroll
    for (int o = 16; o > 0; o >>= 1) lsum += __shfl_xor_sync(0xFFFFFFFFu, lsum, o);
    if (lane == 0) red[wid] = lsum;
    __syncthreads();
    if (wid == 0) {
        float v = (lane < (blockDim.x >> 5)) ? red[lane] : 0.f;
        #pragma unroll
        for (int o = 16; o > 0; o >>= 1) v += __shfl_xor_sync(0xFFFFFFFFu, v, o);
        if (lane == 0) red[0] = v;
    }
    __syncthreads();
    const float inv = 1.0f / red[0];
    for (int i = threadIdx.x; i < S; i += blockDim.x) {
        bf16 h, l; split2(sbuf[i] * inv, h, l);
        ph[i] = h; pl[i] = l;
    }
}

// ---------------- SwiGLU on pairs: gate <- silu(gate)*up ----------------
__global__ void swiglu_pair(bf16* __restrict__ gh, bf16* __restrict__ gl,
                            const bf16* __restrict__ uh, const bf16* __restrict__ ul) {
    size_t i = (size_t)blockIdx.x * blockDim.x + threadIdx.x;
    if (i >= (size_t)S * FF) return;
    float g = join2(gh[i], gl[i]);
    float u = join2(uh[i], ul[i]);
    float r = g / (1.0f + __expf(-g)) * u;
    bf16 h, l; split2(r, h, l);
    gh[i] = h; gl[i] = l;
}

// =================== bf16x3 GEMM, TN ===================
// C[M,N] = alpha * A[M,K] @ B[N,K]^T (+Cadd). Pairs in; fp32 or pair out.
__global__ __launch_bounds__(256, 2)
void gemm_tn_x3(const bf16* __restrict__ Ahi, const bf16* __restrict__ Alo,
                const bf16* __restrict__ Bhi, const bf16* __restrict__ Blo,
                const float* __restrict__ Cadd, float* __restrict__ Cout,
                bf16* __restrict__ Ohi, bf16* __restrict__ Olo,
                int N, int K, float alpha, int outpair) {
    __shared__ __align__(16) bf16 sAh[128 * 40];
    __shared__ __align__(16) bf16 sAl[128 * 40];
    __shared__ __align__(16) bf16 sBh[128 * 40];
    __shared__ __align__(16) bf16 sBl[128 * 40];

    const int tid = threadIdx.x;
    const int lane = tid & 31, wid = tid >> 5;
    const int wm = wid & 3, wn = wid >> 2;
    const int m0 = blockIdx.y * 128, n0 = blockIdx.x * 128;

    float acc[2][8][4];
    #pragma unroll
    for (int i = 0; i < 2; i++)
        #pragma unroll
        for (int j = 0; j < 8; j++)
            #pragma unroll
            for (int l = 0; l < 4; l++) acc[i][j][l] = 0.f;

    const int KT = K >> 5;
    for (int kt = 0; kt < KT; kt++) {
        const int k0 = kt << 5;
        if (kt) __syncthreads();
        #pragma unroll
        for (int i = 0; i < 2; i++) {
            int idx = tid + (i << 8);
            int r = idx >> 2;
            int c8 = (idx & 3) << 3;
            size_t ga = (size_t)(m0 + r) * K + k0 + c8;
            size_t gb = (size_t)(n0 + r) * K + k0 + c8;
            int so = r * 40 + c8;
            *(uint4*)(sAh + so) = *(const uint4*)(Ahi + ga);
            *(uint4*)(sAl + so) = *(const uint4*)(Alo + ga);
            *(uint4*)(sBh + so) = *(const uint4*)(Bhi + gb);
            *(uint4*)(sBl + so) = *(const uint4*)(Blo + gb);
        }
        __syncthreads();
        #pragma unroll
        for (int ks = 0; ks < 2; ks++) {
            unsigned ah[2][4], al[2][4];
            const int arow = lane & 15;
            const int acol = ((lane >> 4) << 3) + (ks << 4);
            #pragma unroll
            for (int mt = 0; mt < 2; mt++) {
                int off = (wm * 32 + mt * 16 + arow) * 40 + acol;
                ldmx4(ah[mt], saddr(sAh + off));
                ldmx4(al[mt], saddr(sAl + off));
            }
            #pragma unroll
            for (int pg = 0; pg < 4; pg++) {
                unsigned bh[4], bl[4];
                int brow = wn * 64 + pg * 16 + ((lane >> 4) << 3) + (lane & 7);
                int bcol = (ks << 4) + ((lane >> 3) & 1) * 8;
                int off = brow * 40 + bcol;
                ldmx4(bh, saddr(sBh + off));
                ldmx4(bl, saddr(sBl + off));
                #pragma unroll
                for (int mt = 0; mt < 2; mt++) {
                    #pragma unroll
                    for (int h = 0; h < 2; h++) {
                        float* c = acc[mt][pg * 2 + h];
                        mma16816(c, ah[mt], bh + h * 2);
                        mma16816(c, ah[mt], bl + h * 2);
                        mma16816(c, al[mt], bh + h * 2);
                    }
                }
            }
        }
    }

    #pragma unroll
    for (int mt = 0; mt < 2; mt++) {
        const int mb = m0 + wm * 32 + mt * 16 + (lane >> 2);
        #pragma unroll
        for (int nt = 0; nt < 8; nt++) {
            const int nb = n0 + wn * 64 + nt * 8 + ((lane & 3) << 1);
            float v0 = acc[mt][nt][0] * alpha;
            float v1 = acc[mt][nt][1] * alpha;
            float v2 = acc[mt][nt][2] * alpha;
            float v3 = acc[mt][nt][3] * alpha;
            if (Cadd) {
                float2 c0 = *(const float2*)(&Cadd[(size_t)mb * N + nb]);
                float2 c1 = *(const float2*)(&Cadd[(size_t)(mb + 8) * N + nb]);
                v0 += c0.x; v1 += c0.y; v2 += c1.x; v3 += c1.y;
            }
            if (outpair) {
                __nv_bfloat162 h01, l01, h23, l23;
                split2(v0, h01.x, l01.x); split2(v1, h01.y, l01.y);
                split2(v2, h23.x, l23.x); split2(v3, h23.y, l23.y);
                *(__nv_bfloat162*)(&Ohi[(size_t)mb * N + nb]) = h01;
                *(__nv_bfloat162*)(&Olo[(size_t)mb * N + nb]) = l01;
                *(__nv_bfloat162*)(&Ohi[(size_t)(mb + 8) * N + nb]) = h23;
                *(__nv_bfloat162*)(&Olo[(size_t)(mb + 8) * N + nb]) = l23;
            } else {
                float2 r0 = {v0, v1}, r1 = {v2, v3};
                *(float2*)(&Cout[(size_t)mb * N + nb]) = r0;
                *(float2*)(&Cout[(size_t)(mb + 8) * N + nb]) = r1;
            }
        }
    }
}

// =================== bf16x3 GEMM, NN (B = [K,N]) ===================
__global__ __launch_bounds__(256, 2)
void gemm_nn_x3(const bf16* __restrict__ Ahi, const bf16* __restrict__ Alo,
                const bf16* __restrict__ Bhi, const bf16* __restrict__ Blo,
                const float* __restrict__ Cadd, float* __restrict__ Cout,
                bf16* __restrict__ Ohi, bf16* __restrict__ Olo,
                int N, int K, float alpha, int outpair) {
    __shared__ __align__(16) bf16 sAh[128 * 40];
    __shared__ __align__(16) bf16 sAl[128 * 40];
    __shared__ __align__(16) bf16 sBh[32 * 136];
    __shared__ __align__(16) bf16 sBl[32 * 136];

    const int tid = threadIdx.x;
    const int lane = tid & 31, wid = tid >> 5;
    const int wm = wid & 3, wn = wid >> 2;
    const int m0 = blockIdx.y * 128, n0 = blockIdx.x * 128;

    float acc[2][8][4];
    #pragma unroll
    for (int i = 0; i < 2; i++)
        #pragma unroll
        for (int j = 0; j < 8; j++)
            #pragma unroll
            for (int l = 0; l < 4; l++) acc[i][j][l] = 0.f;

    const int KT = K >> 5;
    for (int kt = 0; kt < KT; kt++) {
        const int k0 = kt << 5;
        if (kt) __syncthreads();
        #pragma unroll
        for (int i = 0; i < 2; i++) {
            int idx = tid + (i << 8);
            int r = idx >> 2;
            int c8 = (idx & 3) << 3;
            size_t ga = (size_t)(m0 + r) * K + k0 + c8;
            int so = r * 40 + c8;
            *(uint4*)(sAh + so) = *(const uint4*)(Ahi + ga);
            *(uint4*)(sAl + so) = *(const uint4*)(Alo + ga);
            int kr = idx >> 4;
            int nc = (idx & 15) << 3;
            size_t gb = (size_t)(k0 + kr) * N + n0 + nc;
            int sob = kr * 136 + nc;
            *(uint4*)(sBh + sob) = *(const uint4*)(Bhi + gb);
            *(uint4*)(sBl + sob) = *(const uint4*)(Blo + gb);
        }
        __syncthreads();
        #pragma unroll
        for (int ks = 0; ks < 2; ks++) {
            unsigned ah[2][4], al[2][4];
            const int arow = lane & 15;
            const int acol = ((lane >> 4) << 3) + (ks << 4);
            #pragma unroll
            for (int mt = 0; mt < 2; mt++) {
                int off = (wm * 32 + mt * 16 + arow) * 40 + acol;
                ldmx4(ah[mt], saddr(sAh + off));
                ldmx4(al[mt], saddr(sAl + off));
            }
            #pragma unroll
            for (int pg = 0; pg < 4; pg++) {
                unsigned bh[4], bl[4];
                int bk = (ks << 4) + ((lane >> 3) & 1) * 8 + (lane & 7);
                int bn = wn * 64 + pg * 16 + ((lane >> 4) << 3);
                int off = bk * 136 + bn;
                ldmx4t(bh, saddr(sBh + off));
                ldmx4t(bl, saddr(sBl + off));
                #pragma unroll
                for (int mt = 0; mt < 2; mt++) {
                    #pragma unroll
                    for (int h = 0; h < 2; h++) {
                        float* c = acc[mt][pg * 2 + h];
                        mma16816(c, ah[mt], bh + h * 2);
                        mma16816(c, ah[mt], bl + h * 2);
                        mma16816(c, al[mt], bh + h * 2);
                    }
                }
            }
        }
    }

    #pragma unroll
    for (int mt = 0; mt < 2; mt++) {
        const int mb = m0 + wm * 32 + mt * 16 + (lane >> 2);
        #pragma unroll
        for (int nt = 0; nt < 8; nt++) {
            const int nb = n0 + wn * 64 + nt * 8 + ((lane & 3) << 1);
            float v0 = acc[mt][nt][0] * alpha;
            float v1 = acc[mt][nt][1] * alpha;
            float v2 = acc[mt][nt][2] * alpha;
            float v3 = acc[mt][nt][3] * alpha;
            if (Cadd) {
                float2 c0 = *(const float2*)(&Cadd[(size_t)mb * N + nb]);
                float2 c1 = *(const float2*)(&Cadd[(size_t)(mb + 8) * N + nb]);
                v0 += c0.x; v1 += c0.y; v2 += c1.x; v3 += c1.y;
            }
            if (outpair) {
                __nv_bfloat162 h01, l01, h23, l23;
                split2(v0, h01.x, l01.x); split2(v1, h01.y, l01.y);
                split2(v2, h23.x, l23.x); split2(v3, h23.y, l23.y);
                *(__nv_bfloat162*)(&Ohi[(size_t)mb * N + nb]) = h01;
                *(__nv_bfloat162*)(&Olo[(size_t)mb * N + nb]) = l01;
                *(__nv_bfloat162*)(&Ohi[(size_t)(mb + 8) * N + nb]) = h23;
                *(__nv_bfloat162*)(&Olo[(size_t)(mb + 8) * N + nb]) = l23;
            } else {
                float2 r0 = {v0, v1}, r1 = {v2, v3};
                *(float2*)(&Cout[(size_t)mb * N + nb]) = r0;
                *(float2*)(&Cout[(size_t)(mb + 8) * N + nb]) = r1;
            }
        }
    }
}

// ---------------- host launcher ----------------
extern "C" void kernel_launch(void* const* d_in, const int* in_sizes, int n_in,
                              void* d_out, int out_size) {
    const float* x      = (const float*)d_in[0];
    const float* w_rn1  = (const float*)d_in[1];
    const float* wq     = (const float*)d_in[2];
    const float* wk     = (const float*)d_in[3];
    const float* wv     = (const float*)d_in[4];
    const float* wo     = (const float*)d_in[5];
    const float* w_rn2  = (const float*)d_in[6];
    const float* w_gate = (const float*)d_in[7];
    const float* w_up   = (const float*)d_in[8];
    const float* w_down = (const float*)d_in[9];
    const float* cosb   = (const float*)d_in[10];
    const float* sinb   = (const float*)d_in[11];
    float* out = (float*)d_out;

    float* res1;
    cudaGetSymbolAddress((void**)&res1, g_res1);
    bf16 *hb_h, *hb_l, *qb_h, *qb_l, *kb_h, *kb_l, *vb_h, *vb_l, *avb_h, *avb_l;
    bf16 *gateb_h, *gateb_l, *upb_h, *upb_l;
    bf16 *wq_h, *wq_l, *wk_h, *wk_l, *wv_h, *wv_l, *wo_h, *wo_l;
    bf16 *wg_h, *wg_l, *wu_h, *wu_l, *wd_h, *wd_l;
    cudaGetSymbolAddress((void**)&hb_h, g_hb_h);   cudaGetSymbolAddress((void**)&hb_l, g_hb_l);
    cudaGetSymbolAddress((void**)&qb_h, g_qb_h);   cudaGetSymbolAddress((void**)&qb_l, g_qb_l);
    cudaGetSymbolAddress((void**)&kb_h, g_kb_h);   cudaGetSymbolAddress((void**)&kb_l, g_kb_l);
    cudaGetSymbolAddress((void**)&vb_h, g_vb_h);   cudaGetSymbolAddress((void**)&vb_l, g_vb_l);
    cudaGetSymbolAddress((void**)&avb_h, g_avb_h); cudaGetSymbolAddress((void**)&avb_l, g_avb_l);
    cudaGetSymbolAddress((void**)&gateb_h, g_gateb_h); cudaGetSymbolAddress((void**)&gateb_l, g_gateb_l);
    cudaGetSymbolAddress((void**)&upb_h, g_upb_h); cudaGetSymbolAddress((void**)&upb_l, g_upb_l);
    cudaGetSymbolAddress((void**)&wq_h, g_wq_h);   cudaGetSymbolAddress((void**)&wq_l, g_wq_l);
    cudaGetSymbolAddress((void**)&wk_h, g_wk_h);   cudaGetSymbolAddress((void**)&wk_l, g_wk_l);
    cudaGetSymbolAddress((void**)&wv_h, g_wv_h);   cudaGetSymbolAddress((void**)&wv_l, g_wv_l);
    cudaGetSymbolAddress((void**)&wo_h, g_wo_h);   cudaGetSymbolAddress((void**)&wo_l, g_wo_l);
    cudaGetSymbolAddress((void**)&wg_h, g_wg_h);   cudaGetSymbolAddress((void**)&wg_l, g_wg_l);
    cudaGetSymbolAddress((void**)&wu_h, g_wu_h);   cudaGetSymbolAddress((void**)&wu_l, g_wu_l);
    cudaGetSymbolAddress((void**)&wd_h, g_wd_h);   cudaGetSymbolAddress((void**)&wd_l, g_wd_l);

    // attn pair aliases the up pair buffers (disjoint lifetimes)
    bf16* ab_h = upb_h;
    bf16* ab_l = upb_l;

    const float inv_scale = 1.0f / sqrtf((float)D);

    // weight splits
    convert_split4<<<(D * D / 4 + 255) / 256, 256>>>((const float4*)wq, (__nv_bfloat162*)wq_h, (__nv_bfloat162*)wq_l, D * D / 4);
    convert_split4<<<(D * D / 4 + 255) / 256, 256>>>((const float4*)wk, (__nv_bfloat162*)wk_h, (__nv_bfloat162*)wk_l, D * D / 4);
    convert_split4<<<(D * D / 4 + 255) / 256, 256>>>((const float4*)wv, (__nv_bfloat162*)wv_h, (__nv_bfloat162*)wv_l, D * D / 4);
    convert_split4<<<(D * D / 4 + 255) / 256, 256>>>((const float4*)wo, (__nv_bfloat162*)wo_h, (__nv_bfloat162*)wo_l, D * D / 4);
    convert_split4<<<(FF * D / 4 + 255) / 256, 256>>>((const float4*)w_gate, (__nv_bfloat162*)wg_h, (__nv_bfloat162*)wg_l, FF * D / 4);
    convert_split4<<<(FF * D / 4 + 255) / 256, 256>>>((const float4*)w_up,   (__nv_bfloat162*)wu_h, (__nv_bfloat162*)wu_l, FF * D / 4);
    convert_split4<<<(FF * D / 4 + 255) / 256, 256>>>((const float4*)w_down, (__nv_bfloat162*)wd_h, (__nv_bfloat162*)wd_l, FF * D / 4);

    // 1. h = rmsnorm(x)
    rmsnorm_split<<<S, 256>>>(x, w_rn1, hb_h, hb_l);

    // 2-4. q, k, v projections (pair out)
    {
        dim3 grid(D / 128, S / 128);
        gemm_tn_x3<<<grid, 256>>>(hb_h, hb_l, wq_h, wq_l, nullptr, nullptr, qb_h, qb_l, D, D, 1.0f, 1);
        gemm_tn_x3<<<grid, 256>>>(hb_h, hb_l, wk_h, wk_l, nullptr, nullptr, kb_h, kb_l, D, D, 1.0f, 1);
        gemm_tn_x3<<<grid, 256>>>(hb_h, hb_l, wv_h, wv_l, nullptr, nullptr, vb_h, vb_l, D, D, 1.0f, 1);
    }

    // 5. RoPE in place
    rope_pair<<<(S * DH + 255) / 256, 256>>>(qb_h, qb_l, kb_h, kb_l, cosb, sinb);

    // 6. scores = q @ k^T / sqrt(D)  (pair out, into attn alias)
    {
        dim3 grid(S / 128, S / 128);
        gemm_tn_x3<<<grid, 256>>>(qb_h, qb_l, kb_h, kb_l, nullptr, nullptr, ab_h, ab_l, S, D, inv_scale, 1);
    }

    // 7. softmax in place
    softmax_pair<<<S, 256>>>(ab_h, ab_l);

    // 8. av = attn @ v  (NN, pair out)
    {
        dim3 grid(D / 128, S / 128);
        gemm_nn_x3<<<grid, 256>>>(ab_h, ab_l, vb_h, vb_l, nullptr, nullptr, avb_h, avb_l, D, S, 1.0f, 1);
    }

    // 9. res1 = x + av @ wo^T (fp32 out)
    {
        dim3 grid(D / 128, S / 128);
        gemm_tn_x3<<<grid, 256>>>(avb_h, avb_l, wo_h, wo_l, x, res1, nullptr, nullptr, D, D, 1.0f, 0);
    }

    // 10. h = rmsnorm(res1)
    rmsnorm_split<<<S, 256>>>(res1, w_rn2, hb_h, hb_l);

    // 11-12. gate / up projections (pair out; up overwrites attn alias - attn is dead)
    {
        dim3 grid(FF / 128, S / 128);
        gemm_tn_x3<<<grid, 256>>>(hb_h, hb_l, wg_h, wg_l, nullptr, nullptr, gateb_h, gateb_l, FF, D, 1.0f, 1);
        gemm_tn_x3<<<grid, 256>>>(hb_h, hb_l, wu_h, wu_l, nullptr, nullptr, upb_h, upb_l, FF, D, 1.0f, 1);
    }

    // 13. gate <- silu(gate) * up (in place)
    {
        size_t tot = (size_t)S * FF;
        swiglu_pair<<<(unsigned)((tot + 255) / 256), 256>>>(gateb_h, gateb_l, upb_h, upb_l);
    }

    // 14. out = res1 + gate @ w_down^T (fp32 out)
    {
        dim3 grid(D / 128, S / 128);
        gemm_tn_x3<<<grid, 256>>>(gateb_h, gateb_l, wd_h, wd_l, res1, out, nullptr, nullptr, D, FF, 1.0f, 0);
    }
}